// round 16
// baseline (speedup 1.0000x reference)
#include <cuda_runtime.h>
#include <cuda_fp16.h>
#include <math.h>
#include <stdint.h>

// ---------------- problem constants ----------------
#define NN   4096
#define INF_ 512
#define DD   256
#define LL   2
#define HH   8
#define DH   32
#define FF_  1024
#define HALF_ 128

// ---------------- scratch (device global, no allocs) ----------------
#define OFF_H0    0
#define OFF_H     (OFF_H0 + NN*DD)
#define OFF_QKV   (OFF_H  + NN*DD)
#define OFF_ATTN  (OFF_QKV + NN*3*DD)
#define OFF_TMP   (OFF_ATTN + NN*DD)
#define OFF_FF    (OFF_TMP + NN*DD)
#define OFF_WP1T  (OFF_FF + NN*FF_)
#define OFF_KH    (OFF_WP1T + 16384)
#define OFF_VTH   (OFF_KH + 524288)
#define OFF_HCH   (OFF_VTH + 524288)
#define SCRATCH_FLOATS (OFF_HCH + 524288)

__device__ float g_scratch[SCRATCH_FLOATS];

// dynamic smem sizes (bytes)
#define SGEMM_SMEM ((2*128*40 + 2*128*40) * 2)
#define ATTN_SMEM  ((2*64*40 + 2*32*72) * 2)
#define EDGE_BS_H  264
#define EDGE_SMEM  (128*EDGE_BS_H*2 + 2*128*40*2)
#define EDGE_NU    8

// ---------------- fp16 MMA helpers ----------------
__device__ __forceinline__ uint32_t pack_h2(float lo, float hi) {
    __half2 h = __floats2half2_rn(lo, hi);
    return *reinterpret_cast<uint32_t*>(&h);
}

__device__ __forceinline__ void mma_f16(float* d, const uint32_t* a, const uint32_t* b) {
    asm("mma.sync.aligned.m16n8k16.row.col.f32.f16.f16.f32 "
        "{%0,%1,%2,%3},{%4,%5,%6,%7},{%8,%9},{%0,%1,%2,%3};"
        : "+f"(d[0]), "+f"(d[1]), "+f"(d[2]), "+f"(d[3])
        : "r"(a[0]), "r"(a[1]), "r"(a[2]), "r"(a[3]), "r"(b[0]), "r"(b[1]));
}

__device__ __forceinline__ void ldsm_x4(uint32_t* r, uint32_t addr) {
    asm volatile("ldmatrix.sync.aligned.m8n8.x4.shared.b16 {%0,%1,%2,%3}, [%4];"
        : "=r"(r[0]), "=r"(r[1]), "=r"(r[2]), "=r"(r[3]) : "r"(addr));
}

__device__ __forceinline__ uint32_t smem_u32(const void* p) {
    uint32_t a;
    asm("{ .reg .u64 t; cvta.to.shared.u64 t, %1; cvt.u32.u64 %0, t; }" : "=r"(a) : "l"(p));
    return a;
}
__device__ __forceinline__ void cp_async16(uint32_t dst, const void* src) {
    asm volatile("cp.async.ca.shared.global [%0], [%1], 16;" :: "r"(dst), "l"(src));
}
__device__ __forceinline__ void cp_commit() {
    asm volatile("cp.async.commit_group;" ::: "memory");
}
__device__ __forceinline__ void cp_wait0() {
    asm volatile("cp.async.wait_group 0;" ::: "memory");
}
__device__ __forceinline__ void bar_pair(int id) {
    asm volatile("bar.sync %0, 64;" :: "r"(id) : "memory");
}

// ---------------- Wp1 prepass: half, transposed [j][k] ----------------
__global__ __launch_bounds__(256) void wp1_prep_kernel(
    const float* __restrict__ Wp1, __half* __restrict__ wp1t)
{
    int idx = blockIdx.x * 256 + threadIdx.x;
    int k = idx >> 7, j = idx & 127;
    wp1t[j * 256 + k] = __float2half_rn(Wp1[idx]);
}

// ---------------- per-layer KV prepass, smem-tiled V transpose ----------------
__global__ __launch_bounds__(256) void kvprep_kernel(
    const float* __restrict__ qkv, __half* __restrict__ kh, __half* __restrict__ vth)
{
    __shared__ float vt[32][33];
    const int h   = blockIdx.x >> 7;
    const int kv0 = (blockIdx.x & 127) * 32;
    const int tid = threadIdx.x;

    #pragma unroll
    for (int i = 0; i < 4; i++) {
        int kv = (tid >> 5) + i * 8;
        int d  = tid & 31;
        const float* row = qkv + (size_t)(kv0 + kv) * 768 + h * 32;
        kh[(size_t)h * 131072 + (size_t)(kv0 + kv) * 32 + d] = __float2half_rn(row[256 + d]);
        vt[kv][d] = row[512 + d];
    }
    __syncthreads();
    #pragma unroll
    for (int i = 0; i < 4; i++) {
        int d  = (tid >> 5) + i * 8;
        int kv = tid & 31;
        vth[(size_t)h * 131072 + (size_t)d * 4096 + kv0 + kv] = __float2half_rn(vt[kv][d]);
    }
}

// ---------------- fp16 tensor-core SGEMM: BM=128, BN=128, BK=32 ----------------
// 8 warps (4m x 2n), warp tile 32x64, ping-pong + ldmatrix. Single-wave grids.
__global__ __launch_bounds__(256) void sgemm_tc_kernel(
    int M, int N, int K,
    const float* __restrict__ A, const float* __restrict__ B,
    const float* __restrict__ bias, float* __restrict__ C, int act)
{
    extern __shared__ __align__(16) char smraw[];
    __half* As_ = (__half*)smraw;                   // [2][128][40]  ([m][k])
    __half* Bs_ = (__half*)(smraw + 2*128*40*2);    // [2][128][40]  ([n][k])

    const int tid  = threadIdx.x;
    const int lane = tid & 31;
    const int wid  = tid >> 5;
    const int wm   = wid >> 1;      // 0..3
    const int wn   = wid & 1;       // 0..1
    const int grp  = lane >> 2;
    const int tig  = lane & 3;

    const int bx = blockIdx.x, by = blockIdx.y;
    A += (size_t)by * 128 * K;
    B += (size_t)bx * 128;
    C += (size_t)by * 128 * N + (size_t)bx * 128;
    bias += (size_t)bx * 128;

    const uint32_t as_b = smem_u32(As_);
    const uint32_t bs_b = smem_u32(Bs_);
    const int a_row = lane & 15;
    const int a_kh  = (lane >> 4) & 1;
    const int b_n   = (lane & 7) + ((lane >> 4) << 3);
    const int b_kh  = (lane >> 3) & 1;
    uint32_t aAddr[2], bAddr[4];
    #pragma unroll
    for (int mt = 0; mt < 2; mt++)
        aAddr[mt] = as_b + (uint32_t)((wm*32 + mt*16 + a_row) * 40) * 2 + a_kh * 16;
    #pragma unroll
    for (int pr = 0; pr < 4; pr++)
        bAddr[pr] = bs_b + (uint32_t)((wn*64 + pr*16 + b_n) * 40) * 2 + b_kh * 16;

    float acc[2][8][4] = {};
    float4 rA[4], rB[4];

    auto ldT = [&](int kt) {
        #pragma unroll
        for (int i = 0; i < 4; i++) {
            int f = tid + i * 256, r = f >> 3, c4 = f & 7;
            rA[i] = *reinterpret_cast<const float4*>(A + (size_t)r * K + kt + c4 * 4);
        }
        #pragma unroll
        for (int i = 0; i < 4; i++) {
            int f = tid + i * 256, r = f >> 5, c4 = f & 31;
            rB[i] = *reinterpret_cast<const float4*>(B + (size_t)(kt + r) * N + c4 * 4);
        }
    };
    auto stT = [&](int bb) {
        #pragma unroll
        for (int i = 0; i < 4; i++) {
            int f = tid + i * 256, r = f >> 3, c4 = f & 7;
            uint2 u;
            u.x = pack_h2(rA[i].x, rA[i].y);
            u.y = pack_h2(rA[i].z, rA[i].w);
            *reinterpret_cast<uint2*>(&As_[bb*(128*40) + r*40 + c4*4]) = u;
        }
        #pragma unroll
        for (int i = 0; i < 4; i++) {
            int f = tid + i * 256, r = f >> 5, c4 = f & 31;
            __half* bp = &Bs_[bb*(128*40)];
            bp[(c4*4+0)*40 + r] = __float2half_rn(rB[i].x);
            bp[(c4*4+1)*40 + r] = __float2half_rn(rB[i].y);
            bp[(c4*4+2)*40 + r] = __float2half_rn(rB[i].z);
            bp[(c4*4+3)*40 + r] = __float2half_rn(rB[i].w);
        }
    };

    const int T = K / 32;
    ldT(0); stT(0); __syncthreads();

    for (int t = 0; t < T; t++) {
        int cur = t & 1;
        uint32_t curA = cur * (128*40*2);
        uint32_t curB = cur * (128*40*2);
        if (t + 1 < T) ldT((t + 1) * 32);
        #pragma unroll
        for (int ks = 0; ks < 2; ks++) {
            uint32_t a[2][4];
            ldsm_x4(a[0], aAddr[0] + curA + ks*32);
            ldsm_x4(a[1], aAddr[1] + curA + ks*32);
            #pragma unroll
            for (int pr = 0; pr < 4; pr++) {
                uint32_t b[4];
                ldsm_x4(b, bAddr[pr] + curB + ks*32);
                #pragma unroll
                for (int mt = 0; mt < 2; mt++) {
                    mma_f16(acc[mt][pr*2    ], a[mt], b);
                    mma_f16(acc[mt][pr*2 + 1], a[mt], b + 2);
                }
            }
        }
        if (t + 1 < T) stT((t + 1) & 1);
        __syncthreads();
    }

    #pragma unroll
    for (int mt = 0; mt < 2; mt++) {
        #pragma unroll
        for (int nt = 0; nt < 8; nt++) {
            int row = wm * 32 + mt * 16 + grp;
            int col = wn * 64 + nt * 8 + tig * 2;
            float b0 = bias[col], b1 = bias[col+1];
            float2 v0, v1;
            v0.x = acc[mt][nt][0] + b0; v0.y = acc[mt][nt][1] + b1;
            v1.x = acc[mt][nt][2] + b0; v1.y = acc[mt][nt][3] + b1;
            if (act == 1) {
                v0.x = fmaxf(v0.x, 0.f); v0.y = fmaxf(v0.y, 0.f);
                v1.x = fmaxf(v1.x, 0.f); v1.y = fmaxf(v1.y, 0.f);
            }
            *reinterpret_cast<float2*>(C + (size_t)row * N + col)     = v0;
            *reinterpret_cast<float2*>(C + (size_t)(row+8) * N + col) = v1;
        }
    }
}

// ---------------- fp16 MMA flash attention (R13 config: 256 thr, 128-row q) ----------------
__global__ __launch_bounds__(256) void attn_tc_kernel(
    const float* __restrict__ qkv,
    const __half* __restrict__ kh, const __half* __restrict__ vth,
    float* __restrict__ out)
{
    extern __shared__ __align__(16) char smraw[];
    __half* Ks_ = (__half*)smraw;                    // [2][64][40]
    __half* Vs_ = (__half*)(smraw + 2*64*40*2);      // [2][32][72]

    const int h  = blockIdx.y;
    const int qb = blockIdx.x * 128;
    const int tid  = threadIdx.x;
    const int lane = tid & 31;
    const int wid  = tid >> 5;
    const int grp  = lane >> 2;
    const int tig  = lane & 3;
    const float scale = 0.17677669529663687f * 1.4426950408889634f;

    const uint32_t ks_u32 = smem_u32(Ks_);
    const uint32_t vs_u32 = smem_u32(Vs_);
    const __half* khh = kh  + (size_t)h * 131072;
    const __half* vhh = vth + (size_t)h * 131072;

    const int b_n  = (lane & 7) + ((lane >> 4) << 3);
    const int b_kh = (lane >> 3) & 1;
    uint32_t kAddr[4], vAddr[2];
    #pragma unroll
    for (int pr = 0; pr < 4; pr++)
        kAddr[pr] = ks_u32 + (uint32_t)((pr*16 + b_n) * 40) * 2 + b_kh * 16;
    #pragma unroll
    for (int pr = 0; pr < 2; pr++)
        vAddr[pr] = vs_u32 + (uint32_t)((pr*16 + b_n) * 72) * 2 + b_kh * 16;

    uint32_t qa[2][4];
    {
        const float* q0 = qkv + (size_t)(qb + wid*16 + grp) * 768 + h * 32;
        const float* q1 = q0 + (size_t)8 * 768;
        #pragma unroll
        for (int ks = 0; ks < 2; ks++) {
            int b = ks * 16 + 2 * tig;
            qa[ks][0] = pack_h2(q0[b]   * scale, q0[b+1] * scale);
            qa[ks][1] = pack_h2(q1[b]   * scale, q1[b+1] * scale);
            qa[ks][2] = pack_h2(q0[b+8] * scale, q0[b+9] * scale);
            qa[ks][3] = pack_h2(q1[b+8] * scale, q1[b+9] * scale);
        }
    }

    float m0 = -1e30f, m1 = -1e30f, l0 = 0.f, l1 = 0.f;
    float o[4][4] = {};

    auto cpKV = [&](int bb, int kb) {
        int r = tid >> 2, c = tid & 3;
        cp_async16(ks_u32 + (uint32_t)(bb*(64*40) + r*40 + c*8) * 2,
                   khh + (size_t)(kb + r) * 32 + c * 8);
        int r2 = tid >> 3, c2 = tid & 7;
        cp_async16(vs_u32 + (uint32_t)(bb*(32*72) + r2*72 + c2*8) * 2,
                   vhh + (size_t)r2 * 4096 + kb + c2 * 8);
        cp_commit();
    };

    cpKV(0, 0);
    cp_wait0();
    __syncthreads();

    for (int t = 0; t < NN/64; t++) {
        int cur = t & 1;
        uint32_t curK = cur * (64*40*2);
        uint32_t curV = cur * (32*72*2);
        if (t < NN/64 - 1) cpKV(cur ^ 1, (t + 1) * 64);

        float sacc[8][4] = {};
        #pragma unroll
        for (int ks = 0; ks < 2; ks++) {
            #pragma unroll
            for (int pr = 0; pr < 4; pr++) {
                uint32_t b[4];
                ldsm_x4(b, kAddr[pr] + curK + ks*32);
                mma_f16(sacc[pr*2    ], qa[ks], b);
                mma_f16(sacc[pr*2 + 1], qa[ks], b + 2);
            }
        }

        float rmax0 = -1e30f, rmax1 = -1e30f;
        #pragma unroll
        for (int nt = 0; nt < 8; nt++) {
            rmax0 = fmaxf(rmax0, fmaxf(sacc[nt][0], sacc[nt][1]));
            rmax1 = fmaxf(rmax1, fmaxf(sacc[nt][2], sacc[nt][3]));
        }
        rmax0 = fmaxf(rmax0, __shfl_xor_sync(0xffffffffu, rmax0, 1));
        rmax0 = fmaxf(rmax0, __shfl_xor_sync(0xffffffffu, rmax0, 2));
        rmax1 = fmaxf(rmax1, __shfl_xor_sync(0xffffffffu, rmax1, 1));
        rmax1 = fmaxf(rmax1, __shfl_xor_sync(0xffffffffu, rmax1, 2));
        float mn0 = fmaxf(m0, rmax0), mn1 = fmaxf(m1, rmax1);
        float a0 = exp2f(m0 - mn0), a1 = exp2f(m1 - mn1);
        float ps0 = 0.f, ps1 = 0.f;
        uint32_t pa[4][4];
        #pragma unroll
        for (int nt = 0; nt < 8; nt++) {
            float p00 = exp2f(sacc[nt][0] - mn0);
            float p01 = exp2f(sacc[nt][1] - mn0);
            float p10 = exp2f(sacc[nt][2] - mn1);
            float p11 = exp2f(sacc[nt][3] - mn1);
            ps0 += p00 + p01; ps1 += p10 + p11;
            int ks2 = nt >> 1, hf = (nt & 1) * 2;
            pa[ks2][hf + 0] = pack_h2(p00, p01);
            pa[ks2][hf + 1] = pack_h2(p10, p11);
        }
        ps0 += __shfl_xor_sync(0xffffffffu, ps0, 1);
        ps0 += __shfl_xor_sync(0xffffffffu, ps0, 2);
        ps1 += __shfl_xor_sync(0xffffffffu, ps1, 1);
        ps1 += __shfl_xor_sync(0xffffffffu, ps1, 2);
        l0 = l0 * a0 + ps0; l1 = l1 * a1 + ps1;
        m0 = mn0; m1 = mn1;
        #pragma unroll
        for (int nt = 0; nt < 4; nt++) {
            o[nt][0] *= a0; o[nt][1] *= a0;
            o[nt][2] *= a1; o[nt][3] *= a1;
        }

        #pragma unroll
        for (int ks = 0; ks < 4; ks++) {
            #pragma unroll
            for (int pr = 0; pr < 2; pr++) {
                uint32_t b[4];
                ldsm_x4(b, vAddr[pr] + curV + ks*32);
                mma_f16(o[pr*2    ], pa[ks], b);
                mma_f16(o[pr*2 + 1], pa[ks], b + 2);
            }
        }

        if (t < NN/64 - 1) cp_wait0();
        __syncthreads();
    }

    float inv0 = 1.f / l0, inv1 = 1.f / l1;
    int r0 = qb + wid*16 + grp;
    #pragma unroll
    for (int nt = 0; nt < 4; nt++) {
        int col = h * 32 + nt * 8 + tig * 2;
        *reinterpret_cast<float2*>(out + (size_t)r0 * 256 + col) =
            make_float2(o[nt][0] * inv0, o[nt][1] * inv0);
        *reinterpret_cast<float2*>(out + (size_t)(r0 + 8) * 256 + col) =
            make_float2(o[nt][2] * inv1, o[nt][3] * inv1);
    }
}

// ---------------- fused residual-add + LayerNorm (warp per row) ----------------
__global__ __launch_bounds__(256) void add_ln_kernel(
    const float* __restrict__ x, const float* __restrict__ y,
    const float* __restrict__ g, const float* __restrict__ b,
    float* __restrict__ out)
{
    int row = blockIdx.x * 8 + (threadIdx.x >> 5);
    int lid = threadIdx.x & 31;
    const float* xr = x + (size_t)row * 256;
    const float* yr = y + (size_t)row * 256;

    float4 v0 = *reinterpret_cast<const float4*>(xr + lid*4);
    float4 w0 = *reinterpret_cast<const float4*>(yr + lid*4);
    float4 v1 = *reinterpret_cast<const float4*>(xr + 128 + lid*4);
    float4 w1 = *reinterpret_cast<const float4*>(yr + 128 + lid*4);
    float a[8] = { v0.x+w0.x, v0.y+w0.y, v0.z+w0.z, v0.w+w0.w,
                   v1.x+w1.x, v1.y+w1.y, v1.z+w1.z, v1.w+w1.w };

    float s = 0.f;
    #pragma unroll
    for (int i = 0; i < 8; i++) s += a[i];
    #pragma unroll
    for (int o2 = 16; o2 > 0; o2 >>= 1) s += __shfl_xor_sync(0xffffffffu, s, o2);
    float mean = s * (1.f/256.f);

    float q = 0.f;
    #pragma unroll
    for (int i = 0; i < 8; i++) { float d = a[i] - mean; q += d*d; }
    #pragma unroll
    for (int o2 = 16; o2 > 0; o2 >>= 1) q += __shfl_xor_sync(0xffffffffu, q, o2);
    float rstd = rsqrtf(q * (1.f/256.f) + 1e-5f);

    float4 g0 = *reinterpret_cast<const float4*>(g + lid*4);
    float4 b0 = *reinterpret_cast<const float4*>(b + lid*4);
    float4 g1 = *reinterpret_cast<const float4*>(g + 128 + lid*4);
    float4 b1 = *reinterpret_cast<const float4*>(b + 128 + lid*4);
    float4 r0, r1;
    r0.x = (a[0]-mean)*rstd*g0.x + b0.x; r0.y = (a[1]-mean)*rstd*g0.y + b0.y;
    r0.z = (a[2]-mean)*rstd*g0.z + b0.z; r0.w = (a[3]-mean)*rstd*g0.w + b0.w;
    r1.x = (a[4]-mean)*rstd*g1.x + b1.x; r1.y = (a[5]-mean)*rstd*g1.y + b1.y;
    r1.z = (a[6]-mean)*rstd*g1.z + b1.z; r1.w = (a[7]-mean)*rstd*g1.w + b1.w;
    *reinterpret_cast<float4*>(out + (size_t)row*256 + lid*4)       = r0;
    *reinterpret_cast<float4*>(out + (size_t)row*256 + 128 + lid*4) = r1;
}

// final layer: h_combined = LN(x+y) + h0, write fp32 tail + fp16 copy
__global__ __launch_bounds__(256) void add_ln_hc_kernel(
    const float* __restrict__ x, const float* __restrict__ y,
    const float* __restrict__ g, const float* __restrict__ b,
    const float* __restrict__ h0,
    float* __restrict__ out_tail, __half* __restrict__ hch)
{
    int row = blockIdx.x * 8 + (threadIdx.x >> 5);
    int lid = threadIdx.x & 31;
    const float* xr = x + (size_t)row * 256;
    const float* yr = y + (size_t)row * 256;
    const float* hr = h0 + (size_t)row * 256;

    float4 v0 = *reinterpret_cast<const float4*>(xr + lid*4);
    float4 w0 = *reinterpret_cast<const float4*>(yr + lid*4);
    float4 v1 = *reinterpret_cast<const float4*>(xr + 128 + lid*4);
    float4 w1 = *reinterpret_cast<const float4*>(yr + 128 + lid*4);
    float a[8] = { v0.x+w0.x, v0.y+w0.y, v0.z+w0.z, v0.w+w0.w,
                   v1.x+w1.x, v1.y+w1.y, v1.z+w1.z, v1.w+w1.w };

    float s = 0.f;
    #pragma unroll
    for (int i = 0; i < 8; i++) s += a[i];
    #pragma unroll
    for (int o2 = 16; o2 > 0; o2 >>= 1) s += __shfl_xor_sync(0xffffffffu, s, o2);
    float mean = s * (1.f/256.f);

    float q = 0.f;
    #pragma unroll
    for (int i = 0; i < 8; i++) { float d = a[i] - mean; q += d*d; }
    #pragma unroll
    for (int o2 = 16; o2 > 0; o2 >>= 1) q += __shfl_xor_sync(0xffffffffu, q, o2);
    float rstd = rsqrtf(q * (1.f/256.f) + 1e-5f);

    float4 g0 = *reinterpret_cast<const float4*>(g + lid*4);
    float4 b0 = *reinterpret_cast<const float4*>(b + lid*4);
    float4 g1 = *reinterpret_cast<const float4*>(g + 128 + lid*4);
    float4 b1 = *reinterpret_cast<const float4*>(b + 128 + lid*4);
    float4 h00 = *reinterpret_cast<const float4*>(hr + lid*4);
    float4 h01 = *reinterpret_cast<const float4*>(hr + 128 + lid*4);

    float4 c0, c1;
    c0.x = (a[0]-mean)*rstd*g0.x + b0.x + h00.x;
    c0.y = (a[1]-mean)*rstd*g0.y + b0.y + h00.y;
    c0.z = (a[2]-mean)*rstd*g0.z + b0.z + h00.z;
    c0.w = (a[3]-mean)*rstd*g0.w + b0.w + h00.w;
    c1.x = (a[4]-mean)*rstd*g1.x + b1.x + h01.x;
    c1.y = (a[5]-mean)*rstd*g1.y + b1.y + h01.y;
    c1.z = (a[6]-mean)*rstd*g1.z + b1.z + h01.z;
    c1.w = (a[7]-mean)*rstd*g1.w + b1.w + h01.w;

    *reinterpret_cast<float4*>(out_tail + (size_t)row*256 + lid*4)       = c0;
    *reinterpret_cast<float4*>(out_tail + (size_t)row*256 + 128 + lid*4) = c1;

    uint2 u0, u1;
    u0.x = pack_h2(c0.x, c0.y); u0.y = pack_h2(c0.z, c0.w);
    u1.x = pack_h2(c1.x, c1.y); u1.y = pack_h2(c1.z, c1.w);
    *reinterpret_cast<uint2*>(hch + (size_t)row*256 + lid*4)       = u0;
    *reinterpret_cast<uint2*>(hch + (size_t)row*256 + 128 + lid*4) = u1;
}

// ---------------- fused edge predictor: pair-local sync, persistent Wp1 ----------------
__global__ __launch_bounds__(256) void edge_tc_kernel(
    const __half* __restrict__ hch,
    const int* __restrict__ psrc, const int* __restrict__ pdst, const float* __restrict__ pw,
    const int* __restrict__ nsrc, const int* __restrict__ ndst, const float* __restrict__ nw,
    const __half* __restrict__ wp1t, const float* __restrict__ bp1,
    const float* __restrict__ Wp2, const float* __restrict__ bp2,
    float* __restrict__ out, int E, int nblk)
{
    extern __shared__ __align__(16) char smraw[];
    __half* Bs_ = (__half*)smraw;                        // [128][264] persistent
    __half* As_ = (__half*)(smraw + 128*EDGE_BS_H*2);    // [2][128][40]
    __shared__ int      sSrc[128], sDst[128];
    __shared__ uint32_t sWh[128];
    __shared__ float    sWp2[128], sBp1[128];
    __shared__ float    sred[128][2];

    const int tid  = threadIdx.x;
    const int lane = tid & 31;
    const int wid  = tid >> 5;
    const int wm   = wid >> 1;
    const int wn   = wid & 1;
    const int grp  = lane >> 2;
    const int tig  = lane & 3;
    const int pm   = wm;
    const int bar  = 1 + pm;
    const int ptid = tid & 63;

    const uint32_t bs_u32 = smem_u32(Bs_);
    const uint32_t as_u32 = smem_u32(As_);

    const int a_row = lane & 15;
    const int a_kh  = (lane >> 4) & 1;
    const int b_n   = (lane & 7) + ((lane >> 4) << 3);
    const int b_kh  = (lane >> 3) & 1;
    uint32_t aAddr[2], bAddr[4];
    #pragma unroll
    for (int mt = 0; mt < 2; mt++)
        aAddr[mt] = as_u32 + (uint32_t)((pm*32 + mt*16 + a_row) * 40) * 2 + a_kh * 16;
    #pragma unroll
    for (int pr = 0; pr < 4; pr++)
        bAddr[pr] = bs_u32 + (uint32_t)((wn*64 + pr*16 + b_n) * EDGE_BS_H) * 2 + b_kh * 16;

    #pragma unroll
    for (int i = 0; i < 16; i++) {
        int cid = tid + i * 256;
        int j = cid >> 5, c = cid & 31;
        cp_async16(bs_u32 + (uint32_t)(j * EDGE_BS_H + c * 8) * 2,
                   wp1t + (size_t)j * 256 + c * 8);
    }
    cp_commit();
    if (tid < 128) { sWp2[tid] = Wp2[tid]; sBp1[tid] = bp1[tid]; }
    cp_wait0();
    __syncthreads();

    const float bp2v = bp2[0];
    uint4 gs[2], gd[2];

    auto ldA = [&](int kt) {
        #pragma unroll
        for (int i = 0; i < 2; i++) {
            int c = ptid + i * 64;
            int r = pm*32 + (c >> 2), q = c & 3;
            gs[i] = *reinterpret_cast<const uint4*>(hch + (size_t)sSrc[r]*256 + kt*32 + q*8);
            gd[i] = *reinterpret_cast<const uint4*>(hch + (size_t)sDst[r]*256 + kt*32 + q*8);
        }
    };
    auto stA = [&](int bb) {
        #pragma unroll
        for (int i = 0; i < 2; i++) {
            int c = ptid + i * 64;
            int r = pm*32 + (c >> 2), q = c & 3;
            __half2 w2 = *reinterpret_cast<const __half2*>(&sWh[r]);
            const __half2* sp = reinterpret_cast<const __half2*>(&gs[i]);
            const __half2* dp = reinterpret_cast<const __half2*>(&gd[i]);
            uint4 rr;
            __half2* rp = reinterpret_cast<__half2*>(&rr);
            rp[0] = __hmul2(__hmul2(sp[0], dp[0]), w2);
            rp[1] = __hmul2(__hmul2(sp[1], dp[1]), w2);
            rp[2] = __hmul2(__hmul2(sp[2], dp[2]), w2);
            rp[3] = __hmul2(__hmul2(sp[3], dp[3]), w2);
            *reinterpret_cast<uint4*>(&As_[bb*(128*40) + r*40 + q*8]) = rr;
        }
    };

    for (int uu = 0; uu < EDGE_NU; uu++) {
        int u = blockIdx.x * EDGE_NU + uu;
        if (u >= 2 * nblk) break;
        const int pol = (u >= nblk) ? 1 : 0;
        const int blk = u - pol * nblk;
        const int e0  = blk * 128;
        const int* srcA = pol ? nsrc : psrc;
        const int* dstA = pol ? ndst : pdst;
        const float* wA = pol ? nw   : pw;
        float* op = out + (pol ? (size_t)E : 0);

        if (ptid < 32) {
            int r = pm*32 + ptid;
            int e = e0 + r;
            float wv = (e < E) ? wA[e] : 0.f;
            if (e < E) { sSrc[r] = srcA[e]; sDst[r] = dstA[e]; }
            else       { sSrc[r] = 0;       sDst[r] = 0; }
            sWh[r] = pack_h2(wv, wv);
        }
        bar_pair(bar);

        float acc[2][8][4] = {};

        ldA(0);
        stA(0);
        bar_pair(bar);

        for (int t = 0; t < 8; t++) {
            int cur = t & 1;
            uint32_t curA = cur * (128*40*2);
            if (t < 7) ldA(t + 1);
            #pragma unroll
            for (int ks = 0; ks < 2; ks++) {
                uint32_t kb = t*64 + ks*32;
                uint32_t a[2][4];
                ldsm_x4(a[0], aAddr[0] + curA + ks*32);
                ldsm_x4(a[1], aAddr[1] + curA + ks*32);
                #pragma unroll
                for (int pr = 0; pr < 4; pr++) {
                    uint32_t b[4];
                    ldsm_x4(b, bAddr[pr] + kb);
                    #pragma unroll
                    for (int mt = 0; mt < 2; mt++) {
                        mma_f16(acc[mt][pr*2    ], a[mt], b);
                        mma_f16(acc[mt][pr*2 + 1], a[mt], b + 2);
                    }
                }
            }
            if (t < 7) stA((t + 1) & 1);
            bar_pair(bar);
        }

        #pragma unroll
        for (int mt = 0; mt < 2; mt++) {
            float p0 = 0.f, p1 = 0.f;
            #pragma unroll
            for (int nt = 0; nt < 8; nt++) {
                int col = wn * 64 + nt * 8 + tig * 2;
                float bb0 = sBp1[col], bb1 = sBp1[col+1];
                float w0  = sWp2[col], w1  = sWp2[col+1];
                float y;
                y = acc[mt][nt][0] + bb0; y = (y > 0.f) ? y : 0.2f*y; p0 += y * w0;
                y = acc[mt][nt][1] + bb1; y = (y > 0.f) ? y : 0.2f*y; p0 += y * w1;
                y = acc[mt][nt][2] + bb0; y = (y > 0.f) ? y : 0.2f*y; p1 += y * w0;
                y = acc[mt][nt][3] + bb1; y = (y > 0.f) ? y : 0.2f*y; p1 += y * w1;
            }
            p0 += __shfl_xor_sync(0xffffffffu, p0, 1);
            p0 += __shfl_xor_sync(0xffffffffu, p0, 2);
            p1 += __shfl_xor_sync(0xffffffffu, p1, 1);
            p1 += __shfl_xor_sync(0xffffffffu, p1, 2);
            if (tig == 0) {
                int r0 = pm*32 + mt*16 + grp;
                sred[r0    ][wn] = p0;
                sred[r0 + 8][wn] = p1;
            }
        }
        bar_pair(bar);

        if (wn == 0) {
            int r = pm*32 + lane;
            int e = e0 + r;
            if (e < E) op[e] = sred[r][0] + sred[r][1] + bp2v;
        }
        bar_pair(bar);
    }
}

// ---------------- host orchestration ----------------
extern "C" void kernel_launch(void* const* d_in, const int* in_sizes, int n_in,
                              void* d_out, int out_size)
{
    const float* x        = (const float*)d_in[0];
    const int*   pos_src  = (const int*)  d_in[1];
    const int*   pos_dst  = (const int*)  d_in[2];
    const float* pos_w    = (const float*)d_in[3];
    const int*   neg_src  = (const int*)  d_in[4];
    const int*   neg_dst  = (const int*)  d_in[5];
    const float* neg_w    = (const float*)d_in[6];
    const float* Wi       = (const float*)d_in[7];
    const float* bi       = (const float*)d_in[8];
    const float* Wqkv     = (const float*)d_in[9];
    const float* bqkv     = (const float*)d_in[10];
    const float* Wo       = (const float*)d_in[11];
    const float* bo       = (const float*)d_in[12];
    const float* g1       = (const float*)d_in[13];
    const float* be1      = (const float*)d_in[14];
    const float* g2       = (const float*)d_in[15];
    const float* be2      = (const float*)d_in[16];
    const float* W1       = (const float*)d_in[17];
    const float* b1       = (const float*)d_in[18];
    const float* W2       = (const float*)d_in[19];
    const float* b2       = (const float*)d_in[20];
    const float* Wp1      = (const float*)d_in[21];
    const float* bp1      = (const float*)d_in[22];
    const float* Wp2      = (const float*)d_in[23];
    const float* bp2      = (const float*)d_in[24];

    const int E = in_sizes[1];   // 500000

    cudaFuncSetAttribute(sgemm_tc_kernel, cudaFuncAttributeMaxDynamicSharedMemorySize, SGEMM_SMEM);
    cudaFuncSetAttribute(attn_tc_kernel,  cudaFuncAttributeMaxDynamicSharedMemorySize, ATTN_SMEM);
    cudaFuncSetAttribute(edge_tc_kernel,  cudaFuncAttributeMaxDynamicSharedMemorySize, EDGE_SMEM);

    float* S = nullptr;
    cudaGetSymbolAddress((void**)&S, g_scratch);
    float* h0    = S + OFF_H0;
    float* h     = S + OFF_H;
    float* qkv   = S + OFF_QKV;
    float* attn  = S + OFF_ATTN;
    float* tmp   = S + OFF_TMP;
    float* ff    = S + OFF_FF;
    __half* wp1t = (__half*)(S + OFF_WP1T);
    __half* kh   = (__half*)(S + OFF_KH);
    __half* vth  = (__half*)(S + OFF_VTH);
    __half* hch  = (__half*)(S + OFF_HCH);
    float* out   = (float*)d_out;

    wp1_prep_kernel<<<128, 256>>>(Wp1, wp1t);

    sgemm_tc_kernel<<<dim3(DD/128, NN/128), 256, SGEMM_SMEM>>>(NN, DD, INF_, x, Wi, bi, h0, 0);

    for (int l = 0; l < LL; l++) {
        const float* hin = (l == 0) ? h0 : h;
        sgemm_tc_kernel<<<dim3(768/128, NN/128), 256, SGEMM_SMEM>>>(NN, 768, DD,
            hin, Wqkv + (size_t)l*DD*768, bqkv + (size_t)l*768, qkv, 0);
        kvprep_kernel<<<HH * (NN/32), 256>>>(qkv, kh, vth);
        attn_tc_kernel<<<dim3(NN/128, HH), 256, ATTN_SMEM>>>(qkv, kh, vth, attn);
        sgemm_tc_kernel<<<dim3(DD/128, NN/128), 256, SGEMM_SMEM>>>(NN, DD, DD,
            attn, Wo + (size_t)l*DD*DD, bo + (size_t)l*DD, tmp, 0);
        add_ln_kernel<<<NN/8, 256>>>(hin, tmp, g1 + (size_t)l*DD, be1 + (size_t)l*DD, h);
        sgemm_tc_kernel<<<dim3(FF_/128, NN/128), 256, SGEMM_SMEM>>>(NN, FF_, DD,
            h, W1 + (size_t)l*DD*FF_, b1 + (size_t)l*FF_, ff, 1);
        sgemm_tc_kernel<<<dim3(DD/128, NN/128), 256, SGEMM_SMEM>>>(NN, DD, FF_,
            ff, W2 + (size_t)l*FF_*DD, b2 + (size_t)l*DD, tmp, 0);
        if (l == LL - 1) {
            add_ln_hc_kernel<<<NN/8, 256>>>(h, tmp, g2 + (size_t)l*DD, be2 + (size_t)l*DD,
                                            h0, out + 2*(size_t)E, hch);
        } else {
            add_ln_kernel<<<NN/8, 256>>>(h, tmp, g2 + (size_t)l*DD, be2 + (size_t)l*DD, h);
        }
    }

    const int nblk = (E + 127) / 128;
    const int units = 2 * nblk;
    const int egrid = (units + EDGE_NU - 1) / EDGE_NU;
    edge_tc_kernel<<<egrid, 256, EDGE_SMEM>>>(
        hch, pos_src, pos_dst, pos_w, neg_src, neg_dst, neg_w,
        wp1t, bp1, Wp2, bp2, out, E, nblk);
}

// round 17
// speedup vs baseline: 1.1842x; 1.1842x over previous
#include <cuda_runtime.h>
#include <cuda_fp16.h>
#include <math.h>
#include <stdint.h>

// ---------------- problem constants ----------------
#define NN   4096
#define INF_ 512
#define DD   256
#define LL   2
#define HH   8
#define DH   32
#define FF_  1024
#define HALF_ 128

// ---------------- scratch (device global, no allocs) ----------------
#define OFF_H0    0
#define OFF_H     (OFF_H0 + NN*DD)
#define OFF_QKV   (OFF_H  + NN*DD)
#define OFF_ATTN  (OFF_QKV + NN*3*DD)
#define OFF_TMP   (OFF_ATTN + NN*DD)
#define OFF_FF    (OFF_TMP + NN*DD)
#define OFF_WP1T  (OFF_FF + NN*FF_)
#define OFF_KH    (OFF_WP1T + 16384)
#define OFF_VTH   (OFF_KH + 524288)
#define OFF_HCH   (OFF_VTH + 524288)
#define SCRATCH_FLOATS (OFF_HCH + 524288)

__device__ float g_scratch[SCRATCH_FLOATS];

// dynamic smem sizes (bytes)
#define SGEMM_SMEM ((2*128*40 + 2*64*40) * 2)
#define ATTN_SMEM  ((2*64*40 + 2*32*72) * 2)
#define EDGE_BS_H  264
#define EDGE_SMEM  (128*EDGE_BS_H*2 + 2*128*40*2)
#define EDGE_NU    8

// ---------------- fp16 MMA helpers ----------------
__device__ __forceinline__ uint32_t pack_h2(float lo, float hi) {
    __half2 h = __floats2half2_rn(lo, hi);
    return *reinterpret_cast<uint32_t*>(&h);
}

__device__ __forceinline__ void mma_f16(float* d, const uint32_t* a, const uint32_t* b) {
    asm("mma.sync.aligned.m16n8k16.row.col.f32.f16.f16.f32 "
        "{%0,%1,%2,%3},{%4,%5,%6,%7},{%8,%9},{%0,%1,%2,%3};"
        : "+f"(d[0]), "+f"(d[1]), "+f"(d[2]), "+f"(d[3])
        : "r"(a[0]), "r"(a[1]), "r"(a[2]), "r"(a[3]), "r"(b[0]), "r"(b[1]));
}

__device__ __forceinline__ void ldsm_x4(uint32_t* r, uint32_t addr) {
    asm volatile("ldmatrix.sync.aligned.m8n8.x4.shared.b16 {%0,%1,%2,%3}, [%4];"
        : "=r"(r[0]), "=r"(r[1]), "=r"(r[2]), "=r"(r[3]) : "r"(addr));
}

__device__ __forceinline__ uint32_t smem_u32(const void* p) {
    uint32_t a;
    asm("{ .reg .u64 t; cvta.to.shared.u64 t, %1; cvt.u32.u64 %0, t; }" : "=r"(a) : "l"(p));
    return a;
}
__device__ __forceinline__ void cp_async16(uint32_t dst, const void* src) {
    asm volatile("cp.async.ca.shared.global [%0], [%1], 16;" :: "r"(dst), "l"(src));
}
__device__ __forceinline__ void cp_commit() {
    asm volatile("cp.async.commit_group;" ::: "memory");
}
__device__ __forceinline__ void cp_wait0() {
    asm volatile("cp.async.wait_group 0;" ::: "memory");
}
__device__ __forceinline__ void bar_pair(int id) {
    asm volatile("bar.sync %0, 64;" :: "r"(id) : "memory");
}

// ---------------- Wp1 prepass: half, transposed [j][k] ----------------
__global__ __launch_bounds__(256) void wp1_prep_kernel(
    const float* __restrict__ Wp1, __half* __restrict__ wp1t)
{
    int idx = blockIdx.x * 256 + threadIdx.x;
    int k = idx >> 7, j = idx & 127;
    wp1t[j * 256 + k] = __float2half_rn(Wp1[idx]);
}

// ---------------- per-layer KV prepass, smem-tiled V transpose ----------------
__global__ __launch_bounds__(256) void kvprep_kernel(
    const float* __restrict__ qkv, __half* __restrict__ kh, __half* __restrict__ vth)
{
    __shared__ float vt[32][33];
    const int h   = blockIdx.x >> 7;
    const int kv0 = (blockIdx.x & 127) * 32;
    const int tid = threadIdx.x;

    #pragma unroll
    for (int i = 0; i < 4; i++) {
        int kv = (tid >> 5) + i * 8;
        int d  = tid & 31;
        const float* row = qkv + (size_t)(kv0 + kv) * 768 + h * 32;
        kh[(size_t)h * 131072 + (size_t)(kv0 + kv) * 32 + d] = __float2half_rn(row[256 + d]);
        vt[kv][d] = row[512 + d];
    }
    __syncthreads();
    #pragma unroll
    for (int i = 0; i < 4; i++) {
        int d  = (tid >> 5) + i * 8;
        int kv = tid & 31;
        vth[(size_t)h * 131072 + (size_t)d * 4096 + kv0 + kv] = __float2half_rn(vt[kv][d]);
    }
}

// ---------------- fp16 tensor-core SGEMM (R15 config: BM=128, BN=64, BK=32) ----------------
__global__ __launch_bounds__(256) void sgemm_tc_kernel(
    int M, int N, int K,
    const float* __restrict__ A, const float* __restrict__ B,
    const float* __restrict__ bias, float* __restrict__ C, int act)
{
    extern __shared__ __align__(16) char smraw[];
    __half* As_ = (__half*)smraw;                   // [2][128][40]
    __half* Bs_ = (__half*)(smraw + 2*128*40*2);    // [2][64][40]

    const int tid  = threadIdx.x;
    const int lane = tid & 31;
    const int wid  = tid >> 5;
    const int wm   = wid >> 1;
    const int wn   = wid & 1;
    const int grp  = lane >> 2;
    const int tig  = lane & 3;

    const int bx = blockIdx.x, by = blockIdx.y;
    A += (size_t)by * 128 * K;
    B += (size_t)bx * 64;
    C += (size_t)by * 128 * N + (size_t)bx * 64;
    bias += (size_t)bx * 64;

    const uint32_t as_b = smem_u32(As_);
    const uint32_t bs_b = smem_u32(Bs_);
    const int a_row = lane & 15;
    const int a_kh  = (lane >> 4) & 1;
    const int b_n   = (lane & 7) + ((lane >> 4) << 3);
    const int b_kh  = (lane >> 3) & 1;
    uint32_t aAddr[2], bAddr[2];
    #pragma unroll
    for (int mt = 0; mt < 2; mt++)
        aAddr[mt] = as_b + (uint32_t)((wm*32 + mt*16 + a_row) * 40) * 2 + a_kh * 16;
    #pragma unroll
    for (int pr = 0; pr < 2; pr++)
        bAddr[pr] = bs_b + (uint32_t)((wn*32 + pr*16 + b_n) * 40) * 2 + b_kh * 16;

    float acc[2][4][4] = {};
    float4 rA[4], rB[2];

    auto ldT = [&](int kt) {
        #pragma unroll
        for (int i = 0; i < 4; i++) {
            int f = tid + i * 256, r = f >> 3, c4 = f & 7;
            rA[i] = *reinterpret_cast<const float4*>(A + (size_t)r * K + kt + c4 * 4);
        }
        #pragma unroll
        for (int i = 0; i < 2; i++) {
            int f = tid + i * 256, r = f >> 4, c4 = f & 15;
            rB[i] = *reinterpret_cast<const float4*>(B + (size_t)(kt + r) * N + c4 * 4);
        }
    };
    auto stT = [&](int bb) {
        #pragma unroll
        for (int i = 0; i < 4; i++) {
            int f = tid + i * 256, r = f >> 3, c4 = f & 7;
            uint2 u;
            u.x = pack_h2(rA[i].x, rA[i].y);
            u.y = pack_h2(rA[i].z, rA[i].w);
            *reinterpret_cast<uint2*>(&As_[bb*(128*40) + r*40 + c4*4]) = u;
        }
        #pragma unroll
        for (int i = 0; i < 2; i++) {
            int f = tid + i * 256, r = f >> 4, c4 = f & 15;
            __half* bp = &Bs_[bb*(64*40)];
            bp[(c4*4+0)*40 + r] = __float2half_rn(rB[i].x);
            bp[(c4*4+1)*40 + r] = __float2half_rn(rB[i].y);
            bp[(c4*4+2)*40 + r] = __float2half_rn(rB[i].z);
            bp[(c4*4+3)*40 + r] = __float2half_rn(rB[i].w);
        }
    };

    const int T = K / 32;
    ldT(0); stT(0); __syncthreads();

    for (int t = 0; t < T; t++) {
        int cur = t & 1;
        uint32_t curA = cur * (128*40*2);
        uint32_t curB = cur * (64*40*2);
        if (t + 1 < T) ldT((t + 1) * 32);
        #pragma unroll
        for (int ks = 0; ks < 2; ks++) {
            uint32_t a[2][4], b[2][4];
            ldsm_x4(a[0], aAddr[0] + curA + ks*32);
            ldsm_x4(a[1], aAddr[1] + curA + ks*32);
            ldsm_x4(b[0], bAddr[0] + curB + ks*32);
            ldsm_x4(b[1], bAddr[1] + curB + ks*32);
            #pragma unroll
            for (int mt = 0; mt < 2; mt++) {
                mma_f16(acc[mt][0], a[mt], b[0]);
                mma_f16(acc[mt][1], a[mt], b[0] + 2);
                mma_f16(acc[mt][2], a[mt], b[1]);
                mma_f16(acc[mt][3], a[mt], b[1] + 2);
            }
        }
        if (t + 1 < T) stT((t + 1) & 1);
        __syncthreads();
    }

    #pragma unroll
    for (int mt = 0; mt < 2; mt++) {
        #pragma unroll
        for (int nt = 0; nt < 4; nt++) {
            int row = wm * 32 + mt * 16 + grp;
            int col = wn * 32 + nt * 8 + tig * 2;
            float b0 = bias[col], b1 = bias[col+1];
            float2 v0, v1;
            v0.x = acc[mt][nt][0] + b0; v0.y = acc[mt][nt][1] + b1;
            v1.x = acc[mt][nt][2] + b0; v1.y = acc[mt][nt][3] + b1;
            if (act == 1) {
                v0.x = fmaxf(v0.x, 0.f); v0.y = fmaxf(v0.y, 0.f);
                v1.x = fmaxf(v1.x, 0.f); v1.y = fmaxf(v1.y, 0.f);
            }
            *reinterpret_cast<float2*>(C + (size_t)row * N + col)     = v0;
            *reinterpret_cast<float2*>(C + (size_t)(row+8) * N + col) = v1;
        }
    }
}

// ---------------- fp16 MMA flash attention (R15 config: 256 thr, 128-row q) ----------------
__global__ __launch_bounds__(256) void attn_tc_kernel(
    const float* __restrict__ qkv,
    const __half* __restrict__ kh, const __half* __restrict__ vth,
    float* __restrict__ out)
{
    extern __shared__ __align__(16) char smraw[];
    __half* Ks_ = (__half*)smraw;                    // [2][64][40]
    __half* Vs_ = (__half*)(smraw + 2*64*40*2);      // [2][32][72]

    const int h  = blockIdx.y;
    const int qb = blockIdx.x * 128;
    const int tid  = threadIdx.x;
    const int lane = tid & 31;
    const int wid  = tid >> 5;
    const int grp  = lane >> 2;
    const int tig  = lane & 3;
    const float scale = 0.17677669529663687f * 1.4426950408889634f;

    const uint32_t ks_u32 = smem_u32(Ks_);
    const uint32_t vs_u32 = smem_u32(Vs_);
    const __half* khh = kh  + (size_t)h * 131072;
    const __half* vhh = vth + (size_t)h * 131072;

    const int b_n  = (lane & 7) + ((lane >> 4) << 3);
    const int b_kh = (lane >> 3) & 1;
    uint32_t kAddr[4], vAddr[2];
    #pragma unroll
    for (int pr = 0; pr < 4; pr++)
        kAddr[pr] = ks_u32 + (uint32_t)((pr*16 + b_n) * 40) * 2 + b_kh * 16;
    #pragma unroll
    for (int pr = 0; pr < 2; pr++)
        vAddr[pr] = vs_u32 + (uint32_t)((pr*16 + b_n) * 72) * 2 + b_kh * 16;

    uint32_t qa[2][4];
    {
        const float* q0 = qkv + (size_t)(qb + wid*16 + grp) * 768 + h * 32;
        const float* q1 = q0 + (size_t)8 * 768;
        #pragma unroll
        for (int ks = 0; ks < 2; ks++) {
            int b = ks * 16 + 2 * tig;
            float2 a0 = *reinterpret_cast<const float2*>(q0 + b);
            float2 a1 = *reinterpret_cast<const float2*>(q1 + b);
            float2 a2 = *reinterpret_cast<const float2*>(q0 + b + 8);
            float2 a3 = *reinterpret_cast<const float2*>(q1 + b + 8);
            qa[ks][0] = pack_h2(a0.x * scale, a0.y * scale);
            qa[ks][1] = pack_h2(a1.x * scale, a1.y * scale);
            qa[ks][2] = pack_h2(a2.x * scale, a2.y * scale);
            qa[ks][3] = pack_h2(a3.x * scale, a3.y * scale);
        }
    }

    float m0 = -1e30f, m1 = -1e30f, l0 = 0.f, l1 = 0.f;
    float o[4][4] = {};

    auto cpKV = [&](int bb, int kb) {
        int r = tid >> 2, c = tid & 3;
        cp_async16(ks_u32 + (uint32_t)(bb*(64*40) + r*40 + c*8) * 2,
                   khh + (size_t)(kb + r) * 32 + c * 8);
        int r2 = tid >> 3, c2 = tid & 7;
        cp_async16(vs_u32 + (uint32_t)(bb*(32*72) + r2*72 + c2*8) * 2,
                   vhh + (size_t)r2 * 4096 + kb + c2 * 8);
        cp_commit();
    };

    cpKV(0, 0);
    cp_wait0();
    __syncthreads();

    for (int t = 0; t < NN/64; t++) {
        int cur = t & 1;
        uint32_t curK = cur * (64*40*2);
        uint32_t curV = cur * (32*72*2);
        if (t < NN/64 - 1) cpKV(cur ^ 1, (t + 1) * 64);

        float sacc[8][4] = {};
        #pragma unroll
        for (int ks = 0; ks < 2; ks++) {
            #pragma unroll
            for (int pr = 0; pr < 4; pr++) {
                uint32_t b[4];
                ldsm_x4(b, kAddr[pr] + curK + ks*32);
                mma_f16(sacc[pr*2    ], qa[ks], b);
                mma_f16(sacc[pr*2 + 1], qa[ks], b + 2);
            }
        }

        float rmax0 = -1e30f, rmax1 = -1e30f;
        #pragma unroll
        for (int nt = 0; nt < 8; nt++) {
            rmax0 = fmaxf(rmax0, fmaxf(sacc[nt][0], sacc[nt][1]));
            rmax1 = fmaxf(rmax1, fmaxf(sacc[nt][2], sacc[nt][3]));
        }
        rmax0 = fmaxf(rmax0, __shfl_xor_sync(0xffffffffu, rmax0, 1));
        rmax0 = fmaxf(rmax0, __shfl_xor_sync(0xffffffffu, rmax0, 2));
        rmax1 = fmaxf(rmax1, __shfl_xor_sync(0xffffffffu, rmax1, 1));
        rmax1 = fmaxf(rmax1, __shfl_xor_sync(0xffffffffu, rmax1, 2));
        float mn0 = fmaxf(m0, rmax0), mn1 = fmaxf(m1, rmax1);
        float a0 = exp2f(m0 - mn0), a1 = exp2f(m1 - mn1);
        float ps0 = 0.f, ps1 = 0.f;
        uint32_t pa[4][4];
        #pragma unroll
        for (int nt = 0; nt < 8; nt++) {
            float p00 = exp2f(sacc[nt][0] - mn0);
            float p01 = exp2f(sacc[nt][1] - mn0);
            float p10 = exp2f(sacc[nt][2] - mn1);
            float p11 = exp2f(sacc[nt][3] - mn1);
            ps0 += p00 + p01; ps1 += p10 + p11;
            int ks2 = nt >> 1, hf = (nt & 1) * 2;
            pa[ks2][hf + 0] = pack_h2(p00, p01);
            pa[ks2][hf + 1] = pack_h2(p10, p11);
        }
        ps0 += __shfl_xor_sync(0xffffffffu, ps0, 1);
        ps0 += __shfl_xor_sync(0xffffffffu, ps0, 2);
        ps1 += __shfl_xor_sync(0xffffffffu, ps1, 1);
        ps1 += __shfl_xor_sync(0xffffffffu, ps1, 2);
        l0 = l0 * a0 + ps0; l1 = l1 * a1 + ps1;
        m0 = mn0; m1 = mn1;
        #pragma unroll
        for (int nt = 0; nt < 4; nt++) {
            o[nt][0] *= a0; o[nt][1] *= a0;
            o[nt][2] *= a1; o[nt][3] *= a1;
        }

        #pragma unroll
        for (int ks = 0; ks < 4; ks++) {
            #pragma unroll
            for (int pr = 0; pr < 2; pr++) {
                uint32_t b[4];
                ldsm_x4(b, vAddr[pr] + curV + ks*32);
                mma_f16(o[pr*2    ], pa[ks], b);
                mma_f16(o[pr*2 + 1], pa[ks], b + 2);
            }
        }

        if (t < NN/64 - 1) cp_wait0();
        __syncthreads();
    }

    float inv0 = 1.f / l0, inv1 = 1.f / l1;
    int r0 = qb + wid*16 + grp;
    #pragma unroll
    for (int nt = 0; nt < 4; nt++) {
        int col = h * 32 + nt * 8 + tig * 2;
        *reinterpret_cast<float2*>(out + (size_t)r0 * 256 + col) =
            make_float2(o[nt][0] * inv0, o[nt][1] * inv0);
        *reinterpret_cast<float2*>(out + (size_t)(r0 + 8) * 256 + col) =
            make_float2(o[nt][2] * inv1, o[nt][3] * inv1);
    }
}

// ---------------- fused residual-add + LayerNorm (warp per row) ----------------
__global__ __launch_bounds__(256) void add_ln_kernel(
    const float* __restrict__ x, const float* __restrict__ y,
    const float* __restrict__ g, const float* __restrict__ b,
    float* __restrict__ out)
{
    int row = blockIdx.x * 8 + (threadIdx.x >> 5);
    int lid = threadIdx.x & 31;
    const float* xr = x + (size_t)row * 256;
    const float* yr = y + (size_t)row * 256;

    float4 v0 = *reinterpret_cast<const float4*>(xr + lid*4);
    float4 w0 = *reinterpret_cast<const float4*>(yr + lid*4);
    float4 v1 = *reinterpret_cast<const float4*>(xr + 128 + lid*4);
    float4 w1 = *reinterpret_cast<const float4*>(yr + 128 + lid*4);
    float a[8] = { v0.x+w0.x, v0.y+w0.y, v0.z+w0.z, v0.w+w0.w,
                   v1.x+w1.x, v1.y+w1.y, v1.z+w1.z, v1.w+w1.w };

    float s = 0.f;
    #pragma unroll
    for (int i = 0; i < 8; i++) s += a[i];
    #pragma unroll
    for (int o2 = 16; o2 > 0; o2 >>= 1) s += __shfl_xor_sync(0xffffffffu, s, o2);
    float mean = s * (1.f/256.f);

    float q = 0.f;
    #pragma unroll
    for (int i = 0; i < 8; i++) { float d = a[i] - mean; q += d*d; }
    #pragma unroll
    for (int o2 = 16; o2 > 0; o2 >>= 1) q += __shfl_xor_sync(0xffffffffu, q, o2);
    float rstd = rsqrtf(q * (1.f/256.f) + 1e-5f);

    float4 g0 = *reinterpret_cast<const float4*>(g + lid*4);
    float4 b0 = *reinterpret_cast<const float4*>(b + lid*4);
    float4 g1 = *reinterpret_cast<const float4*>(g + 128 + lid*4);
    float4 b1 = *reinterpret_cast<const float4*>(b + 128 + lid*4);
    float4 r0, r1;
    r0.x = (a[0]-mean)*rstd*g0.x + b0.x; r0.y = (a[1]-mean)*rstd*g0.y + b0.y;
    r0.z = (a[2]-mean)*rstd*g0.z + b0.z; r0.w = (a[3]-mean)*rstd*g0.w + b0.w;
    r1.x = (a[4]-mean)*rstd*g1.x + b1.x; r1.y = (a[5]-mean)*rstd*g1.y + b1.y;
    r1.z = (a[6]-mean)*rstd*g1.z + b1.z; r1.w = (a[7]-mean)*rstd*g1.w + b1.w;
    *reinterpret_cast<float4*>(out + (size_t)row*256 + lid*4)       = r0;
    *reinterpret_cast<float4*>(out + (size_t)row*256 + 128 + lid*4) = r1;
}

// final layer: h_combined = LN(x+y) + h0, write fp32 tail + fp16 copy
__global__ __launch_bounds__(256) void add_ln_hc_kernel(
    const float* __restrict__ x, const float* __restrict__ y,
    const float* __restrict__ g, const float* __restrict__ b,
    const float* __restrict__ h0,
    float* __restrict__ out_tail, __half* __restrict__ hch)
{
    int row = blockIdx.x * 8 + (threadIdx.x >> 5);
    int lid = threadIdx.x & 31;
    const float* xr = x + (size_t)row * 256;
    const float* yr = y + (size_t)row * 256;
    const float* hr = h0 + (size_t)row * 256;

    float4 v0 = *reinterpret_cast<const float4*>(xr + lid*4);
    float4 w0 = *reinterpret_cast<const float4*>(yr + lid*4);
    float4 v1 = *reinterpret_cast<const float4*>(xr + 128 + lid*4);
    float4 w1 = *reinterpret_cast<const float4*>(yr + 128 + lid*4);
    float a[8] = { v0.x+w0.x, v0.y+w0.y, v0.z+w0.z, v0.w+w0.w,
                   v1.x+w1.x, v1.y+w1.y, v1.z+w1.z, v1.w+w1.w };

    float s = 0.f;
    #pragma unroll
    for (int i = 0; i < 8; i++) s += a[i];
    #pragma unroll
    for (int o2 = 16; o2 > 0; o2 >>= 1) s += __shfl_xor_sync(0xffffffffu, s, o2);
    float mean = s * (1.f/256.f);

    float q = 0.f;
    #pragma unroll
    for (int i = 0; i < 8; i++) { float d = a[i] - mean; q += d*d; }
    #pragma unroll
    for (int o2 = 16; o2 > 0; o2 >>= 1) q += __shfl_xor_sync(0xffffffffu, q, o2);
    float rstd = rsqrtf(q * (1.f/256.f) + 1e-5f);

    float4 g0 = *reinterpret_cast<const float4*>(g + lid*4);
    float4 b0 = *reinterpret_cast<const float4*>(b + lid*4);
    float4 g1 = *reinterpret_cast<const float4*>(g + 128 + lid*4);
    float4 b1 = *reinterpret_cast<const float4*>(b + 128 + lid*4);
    float4 h00 = *reinterpret_cast<const float4*>(hr + lid*4);
    float4 h01 = *reinterpret_cast<const float4*>(hr + 128 + lid*4);

    float4 c0, c1;
    c0.x = (a[0]-mean)*rstd*g0.x + b0.x + h00.x;
    c0.y = (a[1]-mean)*rstd*g0.y + b0.y + h00.y;
    c0.z = (a[2]-mean)*rstd*g0.z + b0.z + h00.z;
    c0.w = (a[3]-mean)*rstd*g0.w + b0.w + h00.w;
    c1.x = (a[4]-mean)*rstd*g1.x + b1.x + h01.x;
    c1.y = (a[5]-mean)*rstd*g1.y + b1.y + h01.y;
    c1.z = (a[6]-mean)*rstd*g1.z + b1.z + h01.z;
    c1.w = (a[7]-mean)*rstd*g1.w + b1.w + h01.w;

    *reinterpret_cast<float4*>(out_tail + (size_t)row*256 + lid*4)       = c0;
    *reinterpret_cast<float4*>(out_tail + (size_t)row*256 + 128 + lid*4) = c1;

    uint2 u0, u1;
    u0.x = pack_h2(c0.x, c0.y); u0.y = pack_h2(c0.z, c0.w);
    u1.x = pack_h2(c1.x, c1.y); u1.y = pack_h2(c1.z, c1.w);
    *reinterpret_cast<uint2*>(hch + (size_t)row*256 + lid*4)       = u0;
    *reinterpret_cast<uint2*>(hch + (size_t)row*256 + 128 + lid*4) = u1;
}

// ---------------- fused edge predictor: pair-local sync, persistent Wp1 ----------------
__global__ __launch_bounds__(256) void edge_tc_kernel(
    const __half* __restrict__ hch,
    const int* __restrict__ psrc, const int* __restrict__ pdst, const float* __restrict__ pw,
    const int* __restrict__ nsrc, const int* __restrict__ ndst, const float* __restrict__ nw,
    const __half* __restrict__ wp1t, const float* __restrict__ bp1,
    const float* __restrict__ Wp2, const float* __restrict__ bp2,
    float* __restrict__ out, int E, int nblk)
{
    extern __shared__ __align__(16) char smraw[];
    __half* Bs_ = (__half*)smraw;                        // [128][264] persistent
    __half* As_ = (__half*)(smraw + 128*EDGE_BS_H*2);    // [2][128][40]
    __shared__ int      sSrc[128], sDst[128];
    __shared__ uint32_t sWh[128];
    __shared__ float    sWp2[128], sBp1[128];
    __shared__ float    sred[128][2];

    const int tid  = threadIdx.x;
    const int lane = tid & 31;
    const int wid  = tid >> 5;
    const int wm   = wid >> 1;
    const int wn   = wid & 1;
    const int grp  = lane >> 2;
    const int tig  = lane & 3;
    const int pm   = wm;
    const int bar  = 1 + pm;
    const int ptid = tid & 63;

    const uint32_t bs_u32 = smem_u32(Bs_);
    const uint32_t as_u32 = smem_u32(As_);

    const int a_row = lane & 15;
    const int a_kh  = (lane >> 4) & 1;
    const int b_n   = (lane & 7) + ((lane >> 4) << 3);
    const int b_kh  = (lane >> 3) & 1;
    uint32_t aAddr[2], bAddr[4];
    #pragma unroll
    for (int mt = 0; mt < 2; mt++)
        aAddr[mt] = as_u32 + (uint32_t)((pm*32 + mt*16 + a_row) * 40) * 2 + a_kh * 16;
    #pragma unroll
    for (int pr = 0; pr < 4; pr++)
        bAddr[pr] = bs_u32 + (uint32_t)((wn*64 + pr*16 + b_n) * EDGE_BS_H) * 2 + b_kh * 16;

    #pragma unroll
    for (int i = 0; i < 16; i++) {
        int cid = tid + i * 256;
        int j = cid >> 5, c = cid & 31;
        cp_async16(bs_u32 + (uint32_t)(j * EDGE_BS_H + c * 8) * 2,
                   wp1t + (size_t)j * 256 + c * 8);
    }
    cp_commit();
    if (tid < 128) { sWp2[tid] = Wp2[tid]; sBp1[tid] = bp1[tid]; }
    cp_wait0();
    __syncthreads();

    const float bp2v = bp2[0];
    uint4 gs[2], gd[2];

    auto ldA = [&](int kt) {
        #pragma unroll
        for (int i = 0; i < 2; i++) {
            int c = ptid + i * 64;
            int r = pm*32 + (c >> 2), q = c & 3;
            gs[i] = *reinterpret_cast<const uint4*>(hch + (size_t)sSrc[r]*256 + kt*32 + q*8);
            gd[i] = *reinterpret_cast<const uint4*>(hch + (size_t)sDst[r]*256 + kt*32 + q*8);
        }
    };
    auto stA = [&](int bb) {
        #pragma unroll
        for (int i = 0; i < 2; i++) {
            int c = ptid + i * 64;
            int r = pm*32 + (c >> 2), q = c & 3;
            __half2 w2 = *reinterpret_cast<const __half2*>(&sWh[r]);
            const __half2* sp = reinterpret_cast<const __half2*>(&gs[i]);
            const __half2* dp = reinterpret_cast<const __half2*>(&gd[i]);
            uint4 rr;
            __half2* rp = reinterpret_cast<__half2*>(&rr);
            rp[0] = __hmul2(__hmul2(sp[0], dp[0]), w2);
            rp[1] = __hmul2(__hmul2(sp[1], dp[1]), w2);
            rp[2] = __hmul2(__hmul2(sp[2], dp[2]), w2);
            rp[3] = __hmul2(__hmul2(sp[3], dp[3]), w2);
            *reinterpret_cast<uint4*>(&As_[bb*(128*40) + r*40 + q*8]) = rr;
        }
    };

    for (int uu = 0; uu < EDGE_NU; uu++) {
        int u = blockIdx.x * EDGE_NU + uu;
        if (u >= 2 * nblk) break;
        const int pol = (u >= nblk) ? 1 : 0;
        const int blk = u - pol * nblk;
        const int e0  = blk * 128;
        const int* srcA = pol ? nsrc : psrc;
        const int* dstA = pol ? ndst : pdst;
        const float* wA = pol ? nw   : pw;
        float* op = out + (pol ? (size_t)E : 0);

        if (ptid < 32) {
            int r = pm*32 + ptid;
            int e = e0 + r;
            float wv = (e < E) ? wA[e] : 0.f;
            if (e < E) { sSrc[r] = srcA[e]; sDst[r] = dstA[e]; }
            else       { sSrc[r] = 0;       sDst[r] = 0; }
            sWh[r] = pack_h2(wv, wv);
        }
        bar_pair(bar);

        float acc[2][8][4] = {};

        ldA(0);
        stA(0);
        bar_pair(bar);

        for (int t = 0; t < 8; t++) {
            int cur = t & 1;
            uint32_t curA = cur * (128*40*2);
            if (t < 7) ldA(t + 1);
            #pragma unroll
            for (int ks = 0; ks < 2; ks++) {
                uint32_t kb = t*64 + ks*32;
                uint32_t a[2][4];
                ldsm_x4(a[0], aAddr[0] + curA + ks*32);
                ldsm_x4(a[1], aAddr[1] + curA + ks*32);
                #pragma unroll
                for (int pr = 0; pr < 4; pr++) {
                    uint32_t b[4];
                    ldsm_x4(b, bAddr[pr] + kb);
                    #pragma unroll
                    for (int mt = 0; mt < 2; mt++) {
                        mma_f16(acc[mt][pr*2    ], a[mt], b);
                        mma_f16(acc[mt][pr*2 + 1], a[mt], b + 2);
                    }
                }
            }
            if (t < 7) stA((t + 1) & 1);
            bar_pair(bar);
        }

        #pragma unroll
        for (int mt = 0; mt < 2; mt++) {
            float p0 = 0.f, p1 = 0.f;
            #pragma unroll
            for (int nt = 0; nt < 8; nt++) {
                int col = wn * 64 + nt * 8 + tig * 2;
                float bb0 = sBp1[col], bb1 = sBp1[col+1];
                float w0  = sWp2[col], w1  = sWp2[col+1];
                float y;
                y = acc[mt][nt][0] + bb0; y = (y > 0.f) ? y : 0.2f*y; p0 += y * w0;
                y = acc[mt][nt][1] + bb1; y = (y > 0.f) ? y : 0.2f*y; p0 += y * w1;
                y = acc[mt][nt][2] + bb0; y = (y > 0.f) ? y : 0.2f*y; p1 += y * w0;
                y = acc[mt][nt][3] + bb1; y = (y > 0.f) ? y : 0.2f*y; p1 += y * w1;
            }
            p0 += __shfl_xor_sync(0xffffffffu, p0, 1);
            p0 += __shfl_xor_sync(0xffffffffu, p0, 2);
            p1 += __shfl_xor_sync(0xffffffffu, p1, 1);
            p1 += __shfl_xor_sync(0xffffffffu, p1, 2);
            if (tig == 0) {
                int r0 = pm*32 + mt*16 + grp;
                sred[r0    ][wn] = p0;
                sred[r0 + 8][wn] = p1;
            }
        }
        bar_pair(bar);

        if (wn == 0) {
            int r = pm*32 + lane;
            int e = e0 + r;
            if (e < E) op[e] = sred[r][0] + sred[r][1] + bp2v;
        }
        bar_pair(bar);
    }
}

// ---------------- host orchestration ----------------
extern "C" void kernel_launch(void* const* d_in, const int* in_sizes, int n_in,
                              void* d_out, int out_size)
{
    const float* x        = (const float*)d_in[0];
    const int*   pos_src  = (const int*)  d_in[1];
    const int*   pos_dst  = (const int*)  d_in[2];
    const float* pos_w    = (const float*)d_in[3];
    const int*   neg_src  = (const int*)  d_in[4];
    const int*   neg_dst  = (const int*)  d_in[5];
    const float* neg_w    = (const float*)d_in[6];
    const float* Wi       = (const float*)d_in[7];
    const float* bi       = (const float*)d_in[8];
    const float* Wqkv     = (const float*)d_in[9];
    const float* bqkv     = (const float*)d_in[10];
    const float* Wo       = (const float*)d_in[11];
    const float* bo       = (const float*)d_in[12];
    const float* g1       = (const float*)d_in[13];
    const float* be1      = (const float*)d_in[14];
    const float* g2       = (const float*)d_in[15];
    const float* be2      = (const float*)d_in[16];
    const float* W1       = (const float*)d_in[17];
    const float* b1       = (const float*)d_in[18];
    const float* W2       = (const float*)d_in[19];
    const float* b2       = (const float*)d_in[20];
    const float* Wp1      = (const float*)d_in[21];
    const float* bp1      = (const float*)d_in[22];
    const float* Wp2      = (const float*)d_in[23];
    const float* bp2      = (const float*)d_in[24];

    const int E = in_sizes[1];   // 500000

    cudaFuncSetAttribute(sgemm_tc_kernel, cudaFuncAttributeMaxDynamicSharedMemorySize, SGEMM_SMEM);
    cudaFuncSetAttribute(attn_tc_kernel,  cudaFuncAttributeMaxDynamicSharedMemorySize, ATTN_SMEM);
    cudaFuncSetAttribute(edge_tc_kernel,  cudaFuncAttributeMaxDynamicSharedMemorySize, EDGE_SMEM);

    float* S = nullptr;
    cudaGetSymbolAddress((void**)&S, g_scratch);
    float* h0    = S + OFF_H0;
    float* h     = S + OFF_H;
    float* qkv   = S + OFF_QKV;
    float* attn  = S + OFF_ATTN;
    float* tmp   = S + OFF_TMP;
    float* ff    = S + OFF_FF;
    __half* wp1t = (__half*)(S + OFF_WP1T);
    __half* kh   = (__half*)(S + OFF_KH);
    __half* vth  = (__half*)(S + OFF_VTH);
    __half* hch  = (__half*)(S + OFF_HCH);
    float* out   = (float*)d_out;

    wp1_prep_kernel<<<128, 256>>>(Wp1, wp1t);

    sgemm_tc_kernel<<<dim3(DD/64, NN/128), 256, SGEMM_SMEM>>>(NN, DD, INF_, x, Wi, bi, h0, 0);

    for (int l = 0; l < LL; l++) {
        const float* hin = (l == 0) ? h0 : h;
        sgemm_tc_kernel<<<dim3(768/64, NN/128), 256, SGEMM_SMEM>>>(NN, 768, DD,
            hin, Wqkv + (size_t)l*DD*768, bqkv + (size_t)l*768, qkv, 0);
        kvprep_kernel<<<HH * (NN/32), 256>>>(qkv, kh, vth);
        attn_tc_kernel<<<dim3(NN/128, HH), 256, ATTN_SMEM>>>(qkv, kh, vth, attn);
        sgemm_tc_kernel<<<dim3(DD/64, NN/128), 256, SGEMM_SMEM>>>(NN, DD, DD,
            attn, Wo + (size_t)l*DD*DD, bo + (size_t)l*DD, tmp, 0);
        add_ln_kernel<<<NN/8, 256>>>(hin, tmp, g1 + (size_t)l*DD, be1 + (size_t)l*DD, h);
        sgemm_tc_kernel<<<dim3(FF_/64, NN/128), 256, SGEMM_SMEM>>>(NN, FF_, DD,
            h, W1 + (size_t)l*DD*FF_, b1 + (size_t)l*FF_, ff, 1);
        sgemm_tc_kernel<<<dim3(DD/64, NN/128), 256, SGEMM_SMEM>>>(NN, DD, FF_,
            ff, W2 + (size_t)l*FF_*DD, b2 + (size_t)l*DD, tmp, 0);
        if (l == LL - 1) {
            add_ln_hc_kernel<<<NN/8, 256>>>(h, tmp, g2 + (size_t)l*DD, be2 + (size_t)l*DD,
                                            h0, out + 2*(size_t)E, hch);
        } else {
            add_ln_kernel<<<NN/8, 256>>>(h, tmp, g2 + (size_t)l*DD, be2 + (size_t)l*DD, h);
        }
    }

    const int nblk = (E + 127) / 128;
    const int units = 2 * nblk;
    const int egrid = (units + EDGE_NU - 1) / EDGE_NU;
    edge_tc_kernel<<<egrid, 256, EDGE_SMEM>>>(
        hch, pos_src, pos_dst, pos_w, neg_src, neg_dst, neg_w,
        wp1t, bp1, Wp2, bp2, out, E, nblk);
}